// round 1
// baseline (speedup 1.0000x reference)
#include <cuda_runtime.h>

#define DEP   5
#define TOTAL 4096
#define SLOT  5120
#define NSEG  16

// Scratch: mem[b,d,s] = memory_matrix + segment-summed write. 1.6 MB, L2-resident.
__device__ float g_mem[NSEG * DEP * SLOT];

// ---------------------------------------------------------------------------
// K0: initialize scratch with memory_matrix
// ---------------------------------------------------------------------------
__global__ void init_mem_kernel(const float* __restrict__ mm) {
    int i = blockIdx.x * blockDim.x + threadIdx.x;
    if (i < NSEG * DEP * SLOT) g_mem[i] = mm[i];
}

// ---------------------------------------------------------------------------
// K1: scatter (write phase)
// grid = (SLOT/(128*4), DEP, TOTAL/T_CHUNK), block = 128
// Each thread owns 4 consecutive slots; walks T_CHUNK tokens, accumulating in
// registers while the (sorted) segment id is unchanged; flushes via atomicAdd.
// ---------------------------------------------------------------------------
#define T_CHUNK 32
#define SCATTER_THREADS 128

__global__ void scatter_kernel(const float* __restrict__ addr,
                               const float* __restrict__ emb,
                               const float* __restrict__ freq,
                               const int*   __restrict__ seg) {
    __shared__ float s_f[T_CHUNK];
    __shared__ int   s_seg[T_CHUNK];

    const int d  = blockIdx.y;
    const int t0 = blockIdx.z * T_CHUNK;
    const int s0 = blockIdx.x * (SCATTER_THREADS * 4) + threadIdx.x * 4;

    if (threadIdx.x < T_CHUNK) {
        int t = t0 + threadIdx.x;
        s_f[threadIdx.x]   = emb[t * DEP + d] * freq[t];
        s_seg[threadIdx.x] = seg[t];
    }
    __syncthreads();

    const float* base = addr + (size_t)d * TOTAL * SLOT + s0;

    float4 acc = make_float4(0.f, 0.f, 0.f, 0.f);
    int cur = s_seg[0];

    #pragma unroll 4
    for (int i = 0; i < T_CHUNK; ++i) {
        int sg = s_seg[i];
        if (sg != cur) {
            float* g = &g_mem[((size_t)cur * DEP + d) * SLOT + s0];
            atomicAdd(g + 0, acc.x);
            atomicAdd(g + 1, acc.y);
            atomicAdd(g + 2, acc.z);
            atomicAdd(g + 3, acc.w);
            acc = make_float4(0.f, 0.f, 0.f, 0.f);
            cur = sg;
        }
        float  f = s_f[i];
        float4 a = *reinterpret_cast<const float4*>(base + (size_t)(t0 + i) * SLOT);
        acc.x = fmaf(a.x, f, acc.x);
        acc.y = fmaf(a.y, f, acc.y);
        acc.z = fmaf(a.z, f, acc.z);
        acc.w = fmaf(a.w, f, acc.w);
    }
    {
        float* g = &g_mem[((size_t)cur * DEP + d) * SLOT + s0];
        atomicAdd(g + 0, acc.x);
        atomicAdd(g + 1, acc.y);
        atomicAdd(g + 2, acc.z);
        atomicAdd(g + 3, acc.w);
    }
}

// ---------------------------------------------------------------------------
// K2: gather (read phase) + epilogue
// One block per token t. For each d: 5120-length dot of addr[d,t,:] (HBM)
// against g_mem[seg[t],d,:] (L2). Thread 0 writes cm_readhead / cm_info /
// basic_read.
// ---------------------------------------------------------------------------
#define GATHER_THREADS 256

__global__ void gather_kernel(const float* __restrict__ addr,
                              const float* __restrict__ emb,
                              const int*   __restrict__ seg,
                              float*       __restrict__ out) {
    const int t  = blockIdx.x;
    const int sg = seg[t];

    float sums[DEP];

    #pragma unroll
    for (int d = 0; d < DEP; ++d) {
        const float4* a = reinterpret_cast<const float4*>(
            addr + ((size_t)d * TOTAL + t) * SLOT);
        const float4* m = reinterpret_cast<const float4*>(
            g_mem + ((size_t)sg * DEP + d) * SLOT);
        float s = 0.f;
        #pragma unroll
        for (int i = 0; i < SLOT / 4 / GATHER_THREADS; ++i) {  // 5 iters
            int idx = i * GATHER_THREADS + threadIdx.x;
            float4 av = a[idx];
            float4 mv = m[idx];
            s = fmaf(av.x, mv.x, s);
            s = fmaf(av.y, mv.y, s);
            s = fmaf(av.z, mv.z, s);
            s = fmaf(av.w, mv.w, s);
        }
        sums[d] = s;
    }

    __shared__ float red[GATHER_THREADS / 32][DEP];
    int lane = threadIdx.x & 31;
    int wid  = threadIdx.x >> 5;

    #pragma unroll
    for (int d = 0; d < DEP; ++d) {
        float v = sums[d];
        #pragma unroll
        for (int o = 16; o > 0; o >>= 1) v += __shfl_down_sync(0xFFFFFFFFu, v, o);
        if (lane == 0) red[wid][d] = v;
    }
    __syncthreads();

    if (threadIdx.x == 0) {
        float mn = INFINITY;
        float ci[DEP], br[DEP];
        #pragma unroll
        for (int d = 0; d < DEP; ++d) {
            float v = 0.f;
            #pragma unroll
            for (int w = 0; w < GATHER_THREADS / 32; ++w) v += red[w][d];
            br[d] = v;
            ci[d] = v / emb[t * DEP + d];
            mn = fminf(mn, ci[d]);
        }
        // output layout: [cm_readhead (4096)] [cm_info (4096*5)] [basic_read (4096*5)]
        out[t] = mn;
        #pragma unroll
        for (int d = 0; d < DEP; ++d) {
            out[TOTAL + t * DEP + d]               = ci[d];
            out[TOTAL + TOTAL * DEP + t * DEP + d] = br[d];
        }
    }
}

// ---------------------------------------------------------------------------
extern "C" void kernel_launch(void* const* d_in, const int* in_sizes, int n_in,
                              void* d_out, int out_size) {
    const float* addr = (const float*)d_in[0];  // [5, 4096, 5120]
    const float* emb  = (const float*)d_in[1];  // [4096, 5]
    const float* freq = (const float*)d_in[2];  // [4096]
    const float* mm   = (const float*)d_in[3];  // [16, 5, 5120]
    const int*   seg  = (const int*)  d_in[4];  // [4096]
    float* out = (float*)d_out;

    // K0: g_mem = memory_matrix
    init_mem_kernel<<<(NSEG * DEP * SLOT + 255) / 256, 256>>>(mm);

    // K1: scatter
    dim3 sg_grid(SLOT / (SCATTER_THREADS * 4), DEP, TOTAL / T_CHUNK);  // (10, 5, 128)
    scatter_kernel<<<sg_grid, SCATTER_THREADS>>>(addr, emb, freq, seg);

    // K2: gather + epilogue
    gather_kernel<<<TOTAL, GATHER_THREADS>>>(addr, emb, seg, out);
}